// round 15
// baseline (speedup 1.0000x reference)
#include <cuda_runtime.h>
#include <cuda_bf16.h>

// WeaveLayer permutation:
//   out[b, yb*8 + hi*4 + px, xb*8 + wi*4 + py] = in[b, yb*4 + py, xb*4 + px, q=2*hi+wi]
// in (32, 768, 768, 4) f32, out (32, 1536, 1536, 1) f32.
//
// R13: R5 algorithm (output-layout smem tile + conflict-free XOR swizzle) at
// half granularity: CTA = (b, yb, x-half), 256 threads, 24.7 KB smem ->
// 8 CTAs/SM. Finer tiles halve the last-wave drain and let load/store phases
// of co-resident CTAs overlap on each SM (continuous mixed R/W issue).
//
// Swizzle: physical_c4 = c4 ^ f(px), f = px + ((px&2)<<1) in {0,1,6,7}.
// Load lane map: py = tid&3, px = bits 2-3, xb_low = bit 4+ -> each warp's LDG
// covers full 128B lines and each STS hits all reachable banks (bijective over
// lane bits, verified over GF(2); row stride 768 floats === 0 mod 32).

#define B_      32
#define YB      192           // 768 / 4
#define THREADS 256
#define ROWLEN  768           // floats per smem row (one x-half of an output row)

__global__ __launch_bounds__(THREADS, 8) void weave_kernel(
    const float4* __restrict__ in4,   // (32, 768, 768) pixels, 1 float4 each
    float4* __restrict__ out4)        // (32, 1536, 384) float4
{
    __shared__ float smem[8 * ROWLEN];   // 24576 B

    const int bid = blockIdx.x;
    const int xh  = bid & 1;                 // x-half fastest: CTA pairs share rows
    const int yb  = (bid >> 1) % YB;
    const int b   = bid / (2 * YB);
    const int tid = threadIdx.x;

    // ---- Load: 4 rows x 384 px = 1536 float4, 6 iters of 256 ----
    const int in_base = (b * 768 + yb * 4) * 768 + xh * 384;

    #pragma unroll
    for (int k = 0; k < 6; k++) {
        const int i  = tid + k * THREADS;      // 0..1535
        const int py = i & 3;
        const int px = (i >> 2) & 3;
        const int xb = i >> 4;                 // local xb: 0..95
        const int xl = (xb << 2) + px;

        const float4 v = in4[in_base + py * 768 + xl];

        const int f   = px + ((px & 2) << 1);  // {0,1,6,7}
        const int c40 = (xb << 1) ^ f;         // (2*xb + wi=0) ^ f, low3 bits only
        const int a00 = px * ROWLEN + (c40 << 2) + py;          // hi=0, wi=0
        const int a01 = px * ROWLEN + ((c40 ^ 1) << 2) + py;    // hi=0, wi=1

        smem[a00]              = v.x;   // q=0: hi=0, wi=0
        smem[a01]              = v.y;   // q=1: hi=0, wi=1
        smem[a00 + 4 * ROWLEN] = v.z;   // q=2: hi=1, wi=0
        smem[a01 + 4 * ROWLEN] = v.w;   // q=3: hi=1, wi=1
    }

    __syncthreads();

    // ---- Store: 8 rows x 192 float4 = 1536 float4, fully coalesced ----
    const int out_base = (b * 1536 + yb * 8) * 384 + xh * 192;

    #pragma unroll
    for (int k = 0; k < 6; k++) {
        const int j  = tid + k * THREADS;      // 0..1535
        const int r  = j / 192;                // 0..7 (192 % 32 == 0: no straddle)
        const int c4 = j - r * 192;            // 0..191
        const int rp = r & 3;                  // px of this output row
        const int f  = rp + ((rp & 2) << 1);
        const float4 v = *reinterpret_cast<const float4*>(
            &smem[r * ROWLEN + ((c4 ^ f) << 2)]);
        out4[out_base + r * 384 + c4] = v;
    }
}

extern "C" void kernel_launch(void* const* d_in, const int* in_sizes, int n_in,
                              void* d_out, int out_size) {
    const float4* in4 = (const float4*)d_in[0];
    float4* out4 = (float4*)d_out;
    weave_kernel<<<B_ * YB * 2, THREADS>>>(in4, out4);
}